// round 10
// baseline (speedup 1.0000x reference)
#include <cuda_runtime.h>

// ---------------------------------------------------------------------------
// 2-D elastic staggered-grid FDTD, persistent kernel, k=2 time blocking,
// tagged-chunk z-exchange (R8) + WARP-LEVEL X-DECOMPOSITION:
//   256 threads = 8 warps; warp w covers columns [24w-4, 24w+27]
//   (24 owned + 4 ghost columns each side). The 4-deep x-apron lets all 4
//   phases (V1,S1,V2,S2) run warp-internally: every x-neighbor access is a
//   __shfl_up/down_sync, z-neighbors are in registers. Ghost-column validity
//   shrinks 1 column per phase (4->0), covering owned columns at S2.
//   Cross-warp exchange: boundary-owned lanes store their 30-float column
//   state to parity-double-buffered SMEM; ghost lanes reload at iteration
//   start; ONE __syncthreads per iteration (was 4).
//
// z-exchange unchanged: payload+tag in one 16B st/ld.global.cg.v4, slot =
// iter parity, tag==i-1 equality poll (anti-dependency safe: entry into
// iter i data-depends on neighbor having consumed slot i-2).
//
// Ghost-column lanes replicate ALL owner math including source injection.
// Receivers recorded from registers by the owning lane (rec cols distinct).
//
// Output layout (reference): (NT, NREC, 2*B):
//   out[t*NREC*8 + r*8 + comp*4 + b], comp 0 = vx, comp 1 = vz.
// ---------------------------------------------------------------------------

namespace {
constexpr int B_    = 4;
constexpr int NT_   = 256;
constexpr int NZ_   = 192;
constexpr int NX_   = 192;
constexpr int NREC_ = 128;
constexpr int RZ_   = 6;                 // rows per tile
constexpr int NTILES_ = NZ_ / RZ_;       // 32
constexpr int NCTA_   = B_ * NTILES_;    // 128 (< 148 SMs -> all co-resident)
constexpr int NIT_    = NT_ / 2;         // 128 iterations
constexpr int NW_     = 8;               // warps per CTA
constexpr int WOWN_   = 24;              // owned columns per warp
constexpr int NTHR_   = NW_ * 32;        // 256 threads
constexpr float DT_ = 0.001f;
constexpr float DH_ = 10.0f;
}

struct __align__(16) Chunk { float a, b, c; int tag; };

// double-buffered tagged message chunks: [slot][cta][chunk 0..2][x]
__device__ Chunk g_dnC[2][NCTA_][3][NX_];
__device__ Chunk g_upC[2][NCTA_][3][NX_];

__device__ __forceinline__ void ldcg_v4(const Chunk* p, float& a, float& b,
                                        float& c, int& t) {
    asm volatile("ld.global.cg.v4.b32 {%0,%1,%2,%3}, [%4];"
                 : "=f"(a), "=f"(b), "=f"(c), "=r"(t) : "l"(p));
}
__device__ __forceinline__ void stcg_v4(Chunk* p, float a, float b, float c, int t) {
    asm volatile("st.global.cg.v4.b32 [%0], {%1,%2,%3,%4};"
                 :: "l"(p), "f"(a), "f"(b), "f"(c), "r"(t) : "memory");
}
__device__ __forceinline__ float shup(float v) { return __shfl_up_sync(0xffffffffu, v, 1); }
__device__ __forceinline__ float shdn(float v) { return __shfl_down_sync(0xffffffffu, v, 1); }

__global__ void init_msgs_kernel() {
    int i = blockIdx.x * blockDim.x + threadIdx.x;
    int n = 2 * NCTA_ * 3 * NX_ * 4;
    if (i < n) { ((int*)g_dnC)[i] = 0; ((int*)g_upC)[i] = 0; }
}

__global__ void __launch_bounds__(NTHR_, 1) wave_kernel(
    const float* __restrict__ xsrc,    // (B, NT)
    const float* __restrict__ vp,      // (NZ, NX)
    const float* __restrict__ vs,
    const float* __restrict__ rho,
    const int*   __restrict__ src_loc, // (B, 2)
    const int*   __restrict__ rec_loc, // (NREC, 2)
    float*       __restrict__ out)     // (NT, NREC, 2*B)
{
    const int c  = blockIdx.x;
    const int b  = c / NTILES_;
    const int tz = c % NTILES_;
    const int lane = threadIdx.x & 31;
    const int w    = threadIdx.x >> 5;
    const int colRaw = w * WOWN_ + lane - 4;
    const bool valid = (colRaw >= 0) && (colRaw < NX_);
    const int col = valid ? colRaw : (colRaw < 0 ? 0 : NX_ - 1);
    const bool ghost = valid && (lane < 4 || lane >= 28);   // interior ghost cols
    const bool owner = valid && !ghost;
    const bool bnd   = owner && (lane < 8 || lane >= 24);   // ghosted by neighbor warp
    const bool x0 = (col == 0);
    const bool xN = (col == NX_ - 1);
    const bool has_top = (tz > 0);
    const bool has_bot = (tz < NTILES_ - 1);

    // cross-warp column-state exchange, parity double-buffered:
    // [buf][field*6+row][col]; fields: vx,vz,txx,txz,tzz
    __shared__ float s_ex[2][5 * RZ_][NX_];
    for (int idx = threadIdx.x; idx < 2 * 5 * RZ_ * NX_; idx += NTHR_)
        ((float*)s_ex)[idx] = 0.f;

    // per-cell material coefficients (DT, 1/DH folded in) at my column
    float bc[RZ_], cl2m[RZ_], clam[RZ_], cmu[RZ_];
    #pragma unroll
    for (int r = 0; r < RZ_; ++r) {
        int gi = (tz * RZ_ + r) * NX_ + col;
        float vpv = __ldg(&vp[gi]);
        float vsv = __ldg(&vs[gi]);
        float rh  = __ldg(&rho[gi]);
        float mu  = rh * vsv * vsv;
        float lam = rh * (vpv * vpv - 2.0f * vsv * vsv);
        bc[r]   = DT_ / (rh * DH_);
        cl2m[r] = (DT_ / DH_) * (lam + 2.0f * mu);
        clam[r] = (DT_ / DH_) * lam;
        cmu[r]  = (DT_ / DH_) * mu;
    }
    // ghost z-row coefficients: a=z0-1, b=z0-2 (top), p=z1+1, q=z1+2 (bottom)
    float bA=0, bB=0, clamA=0, cl2mA=0, cmuA=0;
    float bP=0, bQ=0, clamP=0, cl2mP=0, cmuP=0;
    if (has_top) {
        int ga = (tz * RZ_ - 1) * NX_ + col;
        int gb = (tz * RZ_ - 2) * NX_ + col;
        float vpv = __ldg(&vp[ga]), vsv = __ldg(&vs[ga]), rh = __ldg(&rho[ga]);
        float mu  = rh * vsv * vsv;
        float lam = rh * (vpv * vpv - 2.0f * vsv * vsv);
        bA = DT_ / (rh * DH_);
        cl2mA = (DT_ / DH_) * (lam + 2.0f * mu);
        clamA = (DT_ / DH_) * lam;
        cmuA  = (DT_ / DH_) * mu;
        bB = DT_ / (__ldg(&rho[gb]) * DH_);
    }
    if (has_bot) {
        int gp = (tz * RZ_ + RZ_) * NX_ + col;
        int gq = (tz * RZ_ + RZ_ + 1) * NX_ + col;
        float vpv = __ldg(&vp[gp]), vsv = __ldg(&vs[gp]), rh = __ldg(&rho[gp]);
        float mu  = rh * vsv * vsv;
        float lam = rh * (vpv * vpv - 2.0f * vsv * vsv);
        bP = DT_ / (rh * DH_);
        cl2mP = (DT_ / DH_) * (lam + 2.0f * mu);
        clamP = (DT_ / DH_) * lam;
        cmuP  = (DT_ / DH_) * mu;
        bQ = DT_ / (__ldg(&rho[gq]) * DH_);
    }

    // wavefields (column strip, registers), zero initial conditions
    float vx[RZ_]  = {}, vz[RZ_]  = {};
    float txx[RZ_] = {}, tzz[RZ_] = {}, txz[RZ_] = {};

    // source ownership by COLUMN (ghost lanes replicate injection)
    const int ssz = src_loc[2 * b];
    const int ssx = src_loc[2 * b + 1];
    const bool is_src = valid && ((ssz / RZ_) == tz) && (col == ssx);
    const int src_lr  = ssz % RZ_;
    const bool src_at_a = valid && has_top && (ssz == tz * RZ_ - 1)  && (col == ssx);
    const bool src_at_p = valid && has_bot && (ssz == tz * RZ_ + RZ_) && (col == ssx);

    // receiver ownership: owning lane of column rx records receiver j
    bool is_rec = false; int rec_j = 0, rec_lrz = 0;
    if (owner) {
        for (int j = 0; j < NREC_; ++j) {
            int rz = __ldg(&rec_loc[2 * j]);
            int rx = __ldg(&rec_loc[2 * j + 1]);
            if (rx == col && (rz / RZ_) == tz) { is_rec = true; rec_j = j; rec_lrz = rz % RZ_; }
        }
    }

    __syncthreads();

    for (int i = 1; i <= NIT_; ++i) {
        const int t1 = 2 * i - 1;
        const int t2 = 2 * i;
        const float w1 = __ldg(&xsrc[b * NT_ + (t1 - 1)]);
        const float w2 = __ldg(&xsrc[b * NT_ + (t2 - 1)]);

        // ---- ghost-column lanes reload full t-state (prev iter's publish) ----
        if (ghost) {
            const float (*ex)[NX_] = s_ex[(i - 1) & 1];
            #pragma unroll
            for (int r = 0; r < RZ_; ++r) {
                vx[r]  = ex[r][col];
                vz[r]  = ex[RZ_ + r][col];
                txx[r] = ex[2 * RZ_ + r][col];
                txz[r] = ex[3 * RZ_ + r][col];
                tzz[r] = ex[4 * RZ_ + r][col];
            }
        }

        // ---- V1 interior rows 1..4 (no z-message dependence) ----
        #pragma unroll
        for (int r = 1; r < RZ_ - 1; ++r) {
            float txx_xp = shdn(txx[r]); if (xN) txx_xp = txx[r];
            float txz_xm = shup(txz[r]); if (x0) txz_xm = txz[r];
            vx[r] += bc[r] * ((txx_xp - txx[r]) + (txz[r] - txz[r - 1]));
            vz[r] += bc[r] * ((txz[r] - txz_xm) + (tzz[r + 1] - tzz[r]));
        }

        // ---- per-lane tagged z-message poll (own column only) ----
        const int want = i - 1;
        const int pr = want & 1;
        float t_vx=0, t_txx=0, t_txz=0, t_vz=0, t_tzz=0, t_txz2=0, t_vz2=0, t_tzz2=0;
        float b_vx=0, b_txx=0, b_txz=0, b_vz=0, b_tzz=0, b_vx2=0, b_txx2=0, b_txz2=0, b_tzz2=0;
        {
            const Chunk* dn = has_top ? &g_dnC[pr][c - 1][0][0] : nullptr;
            const Chunk* up = has_bot ? &g_upC[pr][c + 1][0][0] : nullptr;
            bool tok = !has_top, bok = !has_bot;
            do {
                if (!tok) {
                    int g0, g1, g2; float u;
                    ldcg_v4(dn + 0 * NX_ + col, t_vx,  t_txx,  t_txz,  g0);
                    ldcg_v4(dn + 1 * NX_ + col, t_vz,  t_tzz,  t_txz2, g1);
                    ldcg_v4(dn + 2 * NX_ + col, t_vz2, t_tzz2, u,      g2);
                    tok = (g0 == want) & (g1 == want) & (g2 == want);
                }
                if (!bok) {
                    int g0, g1, g2;
                    ldcg_v4(up + 0 * NX_ + col, b_vx,   b_txx,  b_txz,  g0);
                    ldcg_v4(up + 1 * NX_ + col, b_vz,   b_tzz,  b_vx2,  g1);
                    ldcg_v4(up + 2 * NX_ + col, b_txx2, b_txz2, b_tzz2, g2);
                    bok = (g0 == want) & (g1 == want) & (g2 == want);
                }
            } while (!(tok && bok));
        }
        // x-shifted message values via shuffle (post-reconvergence, uniform)
        float t_txz_xm  = shup(t_txz);  if (x0) t_txz_xm  = t_txz;
        float t_txx_xp  = shdn(t_txx);  if (xN) t_txx_xp  = t_txx;
        float t_txz2_xm = shup(t_txz2); if (x0) t_txz2_xm = t_txz2;
        float b_txz_xm  = shup(b_txz);  if (x0) b_txz_xm  = b_txz;
        float b_txx_xp  = shdn(b_txx);  if (xN) b_txx_xp  = b_txx;
        float b_txx2_xp = shdn(b_txx2); if (xN) b_txx2_xp = b_txx2;

        // ---- ghost t+1 velocities (z-apron rows) ----
        float vza1=0, vzb1=0, vxa1=0, vxp1=0, vxq1=0, vzp1=0;
        if (has_top) {
            vza1 = t_vz  + bA * ((t_txz  - t_txz_xm)  + (tzz[0] - t_tzz));
            vzb1 = t_vz2 + bB * ((t_txz2 - t_txz2_xm) + (t_tzz  - t_tzz2));
            vxa1 = t_vx  + bA * ((t_txx_xp - t_txx)   + (t_txz  - t_txz2));
        }
        if (has_bot) {
            vxp1 = b_vx  + bP * ((b_txx_xp  - b_txx) + (b_txz  - txz[RZ_ - 1]));
            vxq1 = b_vx2 + bQ * ((b_txx2_xp - b_txx2) + (b_txz2 - b_txz));
            vzp1 = b_vz  + bP * ((b_txz - b_txz_xm)  + (b_tzz2 - b_tzz));
        }

        // ---- V1 edge rows 0 and 5 ----
        {
            float txx_xp = shdn(txx[0]); if (xN) txx_xp = txx[0];
            float txz_xm = shup(txz[0]); if (x0) txz_xm = txz[0];
            float txz_zm = has_top ? t_txz : txz[0];
            vx[0] += bc[0] * ((txx_xp - txx[0]) + (txz[0] - txz_zm));
            vz[0] += bc[0] * ((txz[0] - txz_xm) + (tzz[1] - tzz[0]));
        }
        {
            constexpr int r = RZ_ - 1;
            float txx_xp = shdn(txx[r]); if (xN) txx_xp = txx[r];
            float txz_xm = shup(txz[r]); if (x0) txz_xm = txz[r];
            float tzz_zp = has_bot ? b_tzz : tzz[r];
            vx[r] += bc[r] * ((txx_xp - txx[r]) + (txz[r] - txz[r - 1]));
            vz[r] += bc[r] * ((txz[r] - txz_xm) + (tzz_zp - tzz[r]));
        }

        // record t1 (from registers; owning lane)
        if (is_rec) {
            float rvx = 0.f, rvz = 0.f;
            #pragma unroll
            for (int r = 0; r < RZ_; ++r)
                if (r == rec_lrz) { rvx = vx[r]; rvz = vz[r]; }
            int base = (t1 - 1) * (NREC_ * 2 * B_) + rec_j * (2 * B_);
            out[base + b]      = rvx;
            out[base + B_ + b] = rvz;
        }

        // ---- ghost t+1 edge stresses ----
        float tzza1=0, txza1=0, txxp1=0, tzzp1=0, txzp1=0;
        if (has_top) {
            float vxa1_xm = shup(vxa1); if (x0) vxa1_xm = vxa1;
            float vza1_xp = shdn(vza1); if (xN) vza1_xp = vza1;
            tzza1 = t_tzz + clamA * (vxa1 - vxa1_xm) + cl2mA * (vza1 - vzb1);
            if (src_at_a) tzza1 += w1;
            txza1 = t_txz + cmuA * ((vx[0] - vxa1) + (vza1_xp - vza1));
        }
        if (has_bot) {
            float vxp1_xm = shup(vxp1); if (x0) vxp1_xm = vxp1;
            float vzp1_xp = shdn(vzp1); if (xN) vzp1_xp = vzp1;
            float dvx_p = vxp1 - vxp1_xm;
            float dvz_p = vzp1 - vz[RZ_ - 1];
            txxp1 = b_txx + cl2mP * dvx_p + clamP * dvz_p;
            tzzp1 = b_tzz + clamP * dvx_p + cl2mP * dvz_p;
            if (src_at_p) { txxp1 += w1; tzzp1 += w1; }
            txzp1 = b_txz + cmuP * ((vxq1 - vxp1) + (vzp1_xp - vzp1));
        }

        // ------------------ S1 ------------------
        #pragma unroll
        for (int r = 0; r < RZ_; ++r) {
            float vx_xm = shup(vx[r]); if (x0) vx_xm = vx[r];
            float vz_xp = shdn(vz[r]); if (xN) vz_xp = vz[r];
            float vz_zm = (r > 0) ? vz[r - 1] : (has_top ? vza1 : vz[0]);
            float vx_zp = (r < RZ_ - 1) ? vx[r + 1] : (has_bot ? vxp1 : vx[r]);
            float dvx = vx[r] - vx_xm;
            float dvz = vz[r] - vz_zm;
            txx[r] += cl2m[r] * dvx + clam[r] * dvz;
            tzz[r] += clam[r] * dvx + cl2m[r] * dvz;
            txz[r] += cmu[r] * ((vx_zp - vx[r]) + (vz_xp - vz[r]));
            if (is_src && r == src_lr) { txx[r] += w1; tzz[r] += w1; }
        }

        // ---- ghost t+2 edge velocities ----
        float vza2 = 0, vxp2 = 0;
        if (has_top) {
            float txza1_xm = shup(txza1); if (x0) txza1_xm = txza1;
            vza2 = vza1 + bA * ((txza1 - txza1_xm) + (tzz[0] - tzza1));
        }
        if (has_bot) {
            float txxp1_xp = shdn(txxp1); if (xN) txxp1_xp = txxp1;
            vxp2 = vxp1 + bP * ((txxp1_xp - txxp1) + (txzp1 - txz[RZ_ - 1]));
        }

        // ------------------ V2 ------------------
        #pragma unroll
        for (int r = 0; r < RZ_; ++r) {
            float txx_xp = shdn(txx[r]); if (xN) txx_xp = txx[r];
            float txz_xm = shup(txz[r]); if (x0) txz_xm = txz[r];
            float txz_zm = (r > 0) ? txz[r - 1] : (has_top ? txza1 : txz[0]);
            float tzz_zp = (r < RZ_ - 1) ? tzz[r + 1] : (has_bot ? tzzp1 : tzz[r]);
            vx[r] += bc[r] * ((txx_xp - txx[r]) + (txz[r] - txz_zm));
            vz[r] += bc[r] * ((txz[r] - txz_xm) + (tzz_zp - tzz[r]));
        }

        // record t2 (from registers)
        if (is_rec) {
            float rvx = 0.f, rvz = 0.f;
            #pragma unroll
            for (int r = 0; r < RZ_; ++r)
                if (r == rec_lrz) { rvx = vx[r]; rvz = vz[r]; }
            int base = (t2 - 1) * (NREC_ * 2 * B_) + rec_j * (2 * B_);
            out[base + b]      = rvx;
            out[base + B_ + b] = rvz;
        }

        // ------------------ S2 ------------------
        #pragma unroll
        for (int r = 0; r < RZ_; ++r) {
            float vx_xm = shup(vx[r]); if (x0) vx_xm = vx[r];
            float vz_xp = shdn(vz[r]); if (xN) vz_xp = vz[r];
            float vz_zm = (r > 0) ? vz[r - 1] : (has_top ? vza2 : vz[0]);
            float vx_zp = (r < RZ_ - 1) ? vx[r + 1] : (has_bot ? vxp2 : vx[r]);
            float dvx = vx[r] - vx_xm;
            float dvz = vz[r] - vz_zm;
            txx[r] += cl2m[r] * dvx + clam[r] * dvz;
            tzz[r] += clam[r] * dvx + cl2m[r] * dvz;
            txz[r] += cmu[r] * ((vx_zp - vx[r]) + (vz_xp - vz[r]));
            if (is_src && r == src_lr) { txx[r] += w2; tzz[r] += w2; }
        }

        // ---- publish t+2 z-apron (owner lanes; tag travels with payload) ----
        if (owner) {
            const int pw = i & 1;
            Chunk* dn = &g_dnC[pw][c][0][0];
            stcg_v4(dn + 0 * NX_ + col, vx[RZ_-1], txx[RZ_-1], txz[RZ_-1], i);
            stcg_v4(dn + 1 * NX_ + col, vz[RZ_-1], tzz[RZ_-1], txz[RZ_-2], i);
            stcg_v4(dn + 2 * NX_ + col, vz[RZ_-2], tzz[RZ_-2], 0.f,        i);
            Chunk* up = &g_upC[pw][c][0][0];
            stcg_v4(up + 0 * NX_ + col, vx[0],  txx[0], txz[0], i);
            stcg_v4(up + 1 * NX_ + col, vz[0],  tzz[0], vx[1],  i);
            stcg_v4(up + 2 * NX_ + col, txx[1], txz[1], tzz[1], i);
        }

        // ---- publish x-apron state for neighbor warps' ghost columns ----
        if (bnd) {
            float (*ex)[NX_] = s_ex[i & 1];
            #pragma unroll
            for (int r = 0; r < RZ_; ++r) {
                ex[r][col]            = vx[r];
                ex[RZ_ + r][col]      = vz[r];
                ex[2 * RZ_ + r][col]  = txx[r];
                ex[3 * RZ_ + r][col]  = txz[r];
                ex[4 * RZ_ + r][col]  = tzz[r];
            }
        }
        __syncthreads();   // the ONLY barrier per iteration
    }
}

extern "C" void kernel_launch(void* const* d_in, const int* in_sizes, int n_in,
                              void* d_out, int out_size) {
    const float* x   = (const float*)d_in[0];
    const float* vp  = (const float*)d_in[1];
    const float* vs  = (const float*)d_in[2];
    const float* rho = (const float*)d_in[3];
    const int* src   = (const int*)d_in[4];
    const int* rec   = (const int*)d_in[5];
    float* out = (float*)d_out;

    // re-zero message slots (tags -> 0) so every graph replay is identical
    int n = 2 * NCTA_ * 3 * NX_ * 4;
    init_msgs_kernel<<<(n + 255) / 256, 256>>>();
    wave_kernel<<<NCTA_, NTHR_>>>(x, vp, vs, rho, src, rec, out);
}

// round 11
// speedup vs baseline: 3.2828x; 3.2828x over previous
#include <cuda_runtime.h>

// ---------------------------------------------------------------------------
// 2-D elastic staggered-grid FDTD, persistent kernel, k=2 time blocking,
// tagged-chunk single-RTT z-exchange. R8 structure (1 thread per column,
// 6 rows in registers, SMEM x-mirrors) with a deeper poll pipeline:
//   - message loads issued right after barrier A; S1 interior rows 2,3
//     execute before the tag check, hiding the first-attempt RTT;
//   - xm/xp-shifted message values via __shfl of lane neighbors (poll loads
//     halved); warp-boundary lanes do predicated extra loads;
//   - S2 computes rows 4,5 -> publish dn, rows 0,1 -> publish up, then
//     interior rows off the inter-CTA critical path.
// 5 barriers/iter (A..E). Exchange safety unchanged: payload+tag in one 16B
// st/ld.global.cg.v4, slot = iter parity, tag==i-1 equality poll.
//
// Output layout (reference): (NT, NREC, 2*B):
//   out[t*NREC*8 + r*8 + comp*4 + b], comp 0 = vx, comp 1 = vz.
// ---------------------------------------------------------------------------

namespace {
constexpr int B_    = 4;
constexpr int NT_   = 256;
constexpr int NZ_   = 192;
constexpr int NX_   = 192;
constexpr int NREC_ = 128;
constexpr int RZ_   = 6;                 // rows per tile
constexpr int NTILES_ = NZ_ / RZ_;       // 32
constexpr int NCTA_   = B_ * NTILES_;    // 128 (< 148 SMs -> all co-resident)
constexpr int NIT_    = NT_ / 2;         // 128 iterations
constexpr float DT_ = 0.001f;
constexpr float DH_ = 10.0f;
}

struct __align__(16) Chunk { float a, b, c; int tag; };

// double-buffered tagged message chunks: [slot][cta][chunk 0..2][x]
// dn (c -> c+1): {vx5,txx5,txz5} {vz5,tzz5,txz4} {vz4,tzz4,-}
// up (c -> c-1): {vx0,txx0,txz0} {vz0,tzz0,vx1} {txx1,txz1,tzz1}
__device__ Chunk g_dnC[2][NCTA_][3][NX_];
__device__ Chunk g_upC[2][NCTA_][3][NX_];

__device__ __forceinline__ void ldcg_v4(const Chunk* p, float& a, float& b,
                                        float& c, int& t) {
    asm volatile("ld.global.cg.v4.b32 {%0,%1,%2,%3}, [%4];"
                 : "=f"(a), "=f"(b), "=f"(c), "=r"(t) : "l"(p));
}
__device__ __forceinline__ void stcg_v4(Chunk* p, float a, float b, float c, int t) {
    asm volatile("st.global.cg.v4.b32 [%0], {%1,%2,%3,%4};"
                 :: "l"(p), "f"(a), "f"(b), "f"(c), "r"(t) : "memory");
}
__device__ __forceinline__ float shup(float v) { return __shfl_up_sync(0xffffffffu, v, 1); }
__device__ __forceinline__ float shdn(float v) { return __shfl_down_sync(0xffffffffu, v, 1); }

__global__ void init_msgs_kernel() {
    int i = blockIdx.x * blockDim.x + threadIdx.x;
    int n = 2 * NCTA_ * 3 * NX_ * 4;
    if (i < n) { ((int*)g_dnC)[i] = 0; ((int*)g_upC)[i] = 0; }
}

__global__ void __launch_bounds__(NX_, 1) wave_kernel(
    const float* __restrict__ xsrc,    // (B, NT)
    const float* __restrict__ vp,      // (NZ, NX)
    const float* __restrict__ vs,
    const float* __restrict__ rho,
    const int*   __restrict__ src_loc, // (B, 2)
    const int*   __restrict__ rec_loc, // (NREC, 2)
    float*       __restrict__ out)     // (NT, NREC, 2*B)
{
    const int c  = blockIdx.x;
    const int b  = c / NTILES_;
    const int tz = c % NTILES_;
    const int x  = threadIdx.x;
    const int lane = x & 31;
    const bool has_top = (tz > 0);
    const bool has_bot = (tz < NTILES_ - 1);
    const int xm = (x == 0) ? 0 : x - 1;              // clamp -> zero diff at edge
    const int xp = (x == NX_ - 1) ? NX_ - 1 : x + 1;
    const bool lane0e  = (lane == 0)  && (x != 0);        // needs cross-warp xm msg
    const bool lane31e = (lane == 31) && (x != NX_ - 1);  // needs cross-warp xp msg
    const bool x0 = (x == 0);
    const bool xN = (x == NX_ - 1);

    __shared__ float s_vx [RZ_][NX_];
    __shared__ float s_vz [RZ_][NX_];
    __shared__ float s_txx[RZ_][NX_];
    __shared__ float s_txz[RZ_][NX_];
    __shared__ float sh_vxa1[NX_], sh_vza1[NX_], sh_txza1[NX_];
    __shared__ float sh_vxp1[NX_], sh_vzp1[NX_], sh_txxp1[NX_];

    // per-cell material coefficients (DT, 1/DH folded in)
    float bc[RZ_], cl2m[RZ_], clam[RZ_], cmu[RZ_];
    #pragma unroll
    for (int r = 0; r < RZ_; ++r) {
        int gi = (tz * RZ_ + r) * NX_ + x;
        float vpv = __ldg(&vp[gi]);
        float vsv = __ldg(&vs[gi]);
        float rh  = __ldg(&rho[gi]);
        float mu  = rh * vsv * vsv;
        float lam = rh * (vpv * vpv - 2.0f * vsv * vsv);
        bc[r]   = DT_ / (rh * DH_);
        cl2m[r] = (DT_ / DH_) * (lam + 2.0f * mu);
        clam[r] = (DT_ / DH_) * lam;
        cmu[r]  = (DT_ / DH_) * mu;
    }
    // ghost-row coefficients: a=z0-1, b=z0-2 (top), p=z1+1, q=z1+2 (bottom)
    float bA=0, bB=0, clamA=0, cl2mA=0, cmuA=0;
    float bP=0, bQ=0, clamP=0, cl2mP=0, cmuP=0;
    if (has_top) {
        int ga = (tz * RZ_ - 1) * NX_ + x;
        int gb = (tz * RZ_ - 2) * NX_ + x;
        float vpv = __ldg(&vp[ga]), vsv = __ldg(&vs[ga]), rh = __ldg(&rho[ga]);
        float mu  = rh * vsv * vsv;
        float lam = rh * (vpv * vpv - 2.0f * vsv * vsv);
        bA = DT_ / (rh * DH_);
        cl2mA = (DT_ / DH_) * (lam + 2.0f * mu);
        clamA = (DT_ / DH_) * lam;
        cmuA  = (DT_ / DH_) * mu;
        bB = DT_ / (__ldg(&rho[gb]) * DH_);
    }
    if (has_bot) {
        int gp = (tz * RZ_ + RZ_) * NX_ + x;
        int gq = (tz * RZ_ + RZ_ + 1) * NX_ + x;
        float vpv = __ldg(&vp[gp]), vsv = __ldg(&vs[gp]), rh = __ldg(&rho[gp]);
        float mu  = rh * vsv * vsv;
        float lam = rh * (vpv * vpv - 2.0f * vsv * vsv);
        bP = DT_ / (rh * DH_);
        cl2mP = (DT_ / DH_) * (lam + 2.0f * mu);
        clamP = (DT_ / DH_) * lam;
        cmuP  = (DT_ / DH_) * mu;
        bQ = DT_ / (__ldg(&rho[gq]) * DH_);
    }

    // wavefields, zero initial conditions
    float vx[RZ_]  = {}, vz[RZ_]  = {};
    float txx[RZ_] = {}, tzz[RZ_] = {}, txz[RZ_] = {};
    #pragma unroll
    for (int r = 0; r < RZ_; ++r) {
        s_vx[r][x] = 0.f; s_vz[r][x] = 0.f; s_txx[r][x] = 0.f; s_txz[r][x] = 0.f;
    }

    // source ownership
    const int ssz = src_loc[2 * b];
    const int ssx = src_loc[2 * b + 1];
    const bool is_src = ((ssz / RZ_) == tz) && (x == ssx);
    const int src_lr  = ssz % RZ_;
    const bool src_at_a = has_top && (ssz == tz * RZ_ - 1)  && (x == ssx);
    const bool src_at_p = has_bot && (ssz == tz * RZ_ + RZ_) && (x == ssx);

    // receiver ownership: thread index doubles as receiver index
    bool is_rec = false;
    int my_lrz = 0, my_rx = 0;
    if (x < NREC_) {
        int rz = rec_loc[2 * x];
        my_rx  = rec_loc[2 * x + 1];
        if ((rz / RZ_) == tz) { is_rec = true; my_lrz = rz % RZ_; }
    }

    __syncthreads();

    for (int i = 1; i <= NIT_; ++i) {
        const int t1 = 2 * i - 1;
        const int t2 = 2 * i;
        const float w1 = __ldg(&xsrc[b * NT_ + (t1 - 1)]);
        const float w2 = __ldg(&xsrc[b * NT_ + (t2 - 1)]);

        // ---- V1 interior rows 1..4 (no message dependence) + mirror stores ----
        #pragma unroll
        for (int r = 1; r < RZ_ - 1; ++r) {
            float txx_c = txx[r], txz_c = txz[r];
            vx[r] += bc[r] * ((s_txx[r][xp] - txx_c) + (txz_c - txz[r - 1]));
            vz[r] += bc[r] * ((txz_c - s_txz[r][xm]) + (tzz[r + 1] - tzz[r]));
            s_vx[r][x] = vx[r]; s_vz[r][x] = vz[r];
        }
        __syncthreads();   // (A)

        // ---- issue first-attempt message loads (RTT overlaps S1 rows 2,3) ----
        const int want = i - 1;
        const int pr = want & 1;
        const Chunk* dn = has_top ? &g_dnC[pr][c - 1][0][0] : nullptr;
        const Chunk* up = has_bot ? &g_upC[pr][c + 1][0][0] : nullptr;
        float t_vx=0, t_txx=0, t_txz=0, t_vz=0, t_tzz=0, t_txz2=0, t_vz2=0, t_tzz2=0;
        float b_vx=0, b_txx=0, b_txz=0, b_vz=0, b_tzz=0, b_vx2=0, b_txx2=0, b_txz2=0, b_tzz2=0;
        float e_t_txz_xm=0, e_t_txz2_xm=0, e_t_txx_xp=0;
        float e_b_txz_xm=0, e_b_txx_xp=0, e_b_txx2_xp=0;
        int g0=want, g1=want, g2=want, g3=want, g4=want;
        int h0=want, h1=want, h2=want, h3=want, h4=want;
        float u0, u1, u2;
        if (has_top) {
            ldcg_v4(dn + 0 * NX_ + x, t_vx,  t_txx,  t_txz,  g0);
            ldcg_v4(dn + 1 * NX_ + x, t_vz,  t_tzz,  t_txz2, g1);
            ldcg_v4(dn + 2 * NX_ + x, t_vz2, t_tzz2, u0,     g2);
            if (lane0e) {
                ldcg_v4(dn + 0 * NX_ + xm, u0, u1, e_t_txz_xm,  g3);
                ldcg_v4(dn + 1 * NX_ + xm, u0, u1, e_t_txz2_xm, g4);
            }
            if (lane31e) ldcg_v4(dn + 0 * NX_ + xp, u0, e_t_txx_xp, u1, g3);
        }
        if (has_bot) {
            ldcg_v4(up + 0 * NX_ + x, b_vx,   b_txx,  b_txz,  h0);
            ldcg_v4(up + 1 * NX_ + x, b_vz,   b_tzz,  b_vx2,  h1);
            ldcg_v4(up + 2 * NX_ + x, b_txx2, b_txz2, b_tzz2, h2);
            if (lane0e) ldcg_v4(up + 0 * NX_ + xm, u0, u1, e_b_txz_xm, h3);
            if (lane31e) {
                ldcg_v4(up + 0 * NX_ + xp, u0, e_b_txx_xp, u1, h3);
                ldcg_v4(up + 2 * NX_ + xp, e_b_txx2_xp, u1, u2, h4);
            }
        }

        // ---- S1 rows 2,3 (needs only interior data; mirrors valid via bar A) ----
        #pragma unroll
        for (int r = 2; r < RZ_ - 2; ++r) {
            float dvx = vx[r] - s_vx[r][xm];
            float dvz = vz[r] - vz[r - 1];
            txx[r] += cl2m[r] * dvx + clam[r] * dvz;
            tzz[r] += clam[r] * dvx + cl2m[r] * dvz;
            txz[r] += cmu[r] * ((vx[r + 1] - vx[r]) + (s_vz[r][xp] - vz[r]));
            if (is_src && r == src_lr) { txx[r] += w1; tzz[r] += w1; }
        }

        // ---- tag check; retry only if stale ----
        bool tok = !has_top ||
            ((g0 == want) & (g1 == want) & (g2 == want) & (g3 == want) & (g4 == want));
        bool bok = !has_bot ||
            ((h0 == want) & (h1 == want) & (h2 == want) & (h3 == want) & (h4 == want));
        while (!(tok && bok)) {
            if (!tok) {
                g3 = want; g4 = want;
                ldcg_v4(dn + 0 * NX_ + x, t_vx,  t_txx,  t_txz,  g0);
                ldcg_v4(dn + 1 * NX_ + x, t_vz,  t_tzz,  t_txz2, g1);
                ldcg_v4(dn + 2 * NX_ + x, t_vz2, t_tzz2, u0,     g2);
                if (lane0e) {
                    ldcg_v4(dn + 0 * NX_ + xm, u0, u1, e_t_txz_xm,  g3);
                    ldcg_v4(dn + 1 * NX_ + xm, u0, u1, e_t_txz2_xm, g4);
                }
                if (lane31e) ldcg_v4(dn + 0 * NX_ + xp, u0, e_t_txx_xp, u1, g3);
                tok = (g0 == want) & (g1 == want) & (g2 == want) & (g3 == want) & (g4 == want);
            }
            if (!bok) {
                h3 = want; h4 = want;
                ldcg_v4(up + 0 * NX_ + x, b_vx,   b_txx,  b_txz,  h0);
                ldcg_v4(up + 1 * NX_ + x, b_vz,   b_tzz,  b_vx2,  h1);
                ldcg_v4(up + 2 * NX_ + x, b_txx2, b_txz2, b_tzz2, h2);
                if (lane0e) ldcg_v4(up + 0 * NX_ + xm, u0, u1, e_b_txz_xm, h3);
                if (lane31e) {
                    ldcg_v4(up + 0 * NX_ + xp, u0, e_b_txx_xp, u1, h3);
                    ldcg_v4(up + 2 * NX_ + xp, e_b_txx2_xp, u1, u2, h4);
                }
                bok = (h0 == want) & (h1 == want) & (h2 == want) & (h3 == want) & (h4 == want);
            }
        }

        // ---- x-shifted message values via shuffles (warp converged here) ----
        float t_txz_xm  = shup(t_txz);
        float t_txx_xp  = shdn(t_txx);
        float t_txz2_xm = shup(t_txz2);
        float b_txz_xm  = shup(b_txz);
        float b_txx_xp  = shdn(b_txx);
        float b_txx2_xp = shdn(b_txx2);
        if (lane == 0) {
            t_txz_xm  = x0 ? t_txz  : e_t_txz_xm;
            t_txz2_xm = x0 ? t_txz2 : e_t_txz2_xm;
            b_txz_xm  = x0 ? b_txz  : e_b_txz_xm;
        }
        if (lane == 31) {
            t_txx_xp  = xN ? t_txx  : e_t_txx_xp;
            b_txx_xp  = xN ? b_txx  : e_b_txx_xp;
            b_txx2_xp = xN ? b_txx2 : e_b_txx2_xp;
        }

        // ---- ghost t+1 velocities ----
        float vza1=0, vzb1=0, vxa1=0, vxp1=0, vxq1=0, vzp1=0;
        if (has_top) {
            vza1 = t_vz  + bA * ((t_txz  - t_txz_xm)  + (tzz[0] - t_tzz));
            vzb1 = t_vz2 + bB * ((t_txz2 - t_txz2_xm) + (t_tzz  - t_tzz2));
            vxa1 = t_vx  + bA * ((t_txx_xp - t_txx)   + (t_txz  - t_txz2));
        }
        if (has_bot) {
            vxp1 = b_vx  + bP * ((b_txx_xp  - b_txx)  + (b_txz  - txz[RZ_ - 1]));
            vxq1 = b_vx2 + bQ * ((b_txx2_xp - b_txx2) + (b_txz2 - b_txz));
            vzp1 = b_vz  + bP * ((b_txz - b_txz_xm)   + (b_tzz2 - b_tzz));
        }

        // ---- V1 edge rows 0, 5 + mirror stores + ghost staging ----
        {
            float txz_zm = has_top ? t_txz : txz[0];
            vx[0] += bc[0] * ((s_txx[0][xp] - txx[0]) + (txz[0] - txz_zm));
            vz[0] += bc[0] * ((txz[0] - s_txz[0][xm]) + (tzz[1] - tzz[0]));
            constexpr int r = RZ_ - 1;
            float tzz_zp = has_bot ? b_tzz : tzz[r];
            vx[r] += bc[r] * ((s_txx[r][xp] - txx[r]) + (txz[r] - txz[r - 1]));
            vz[r] += bc[r] * ((txz[r] - s_txz[r][xm]) + (tzz_zp - tzz[r]));
        }
        s_vx[0][x] = vx[0];             s_vz[0][x] = vz[0];
        s_vx[RZ_ - 1][x] = vx[RZ_ - 1]; s_vz[RZ_ - 1][x] = vz[RZ_ - 1];
        sh_vxa1[x] = vxa1; sh_vza1[x] = vza1;
        sh_vxp1[x] = vxp1; sh_vzp1[x] = vzp1;
        __syncthreads();   // (B)

        // record t1
        if (is_rec) {
            int base = (t1 - 1) * (NREC_ * 2 * B_) + x * (2 * B_);
            out[base + b]      = s_vx[my_lrz][my_rx];
            out[base + B_ + b] = s_vz[my_lrz][my_rx];
        }

        // ---- ghost t+1 edge stresses ----
        float tzza1=0, txza1=0, txxp1=0, tzzp1=0, txzp1=0;
        if (has_top) {
            tzza1 = t_tzz + clamA * (vxa1 - sh_vxa1[xm]) + cl2mA * (vza1 - vzb1);
            if (src_at_a) tzza1 += w1;
            txza1 = t_txz + cmuA * ((vx[0] - vxa1) + (sh_vza1[xp] - vza1));
        }
        if (has_bot) {
            float dvx_p = vxp1 - sh_vxp1[xm];
            float dvz_p = vzp1 - vz[RZ_ - 1];
            txxp1 = b_txx + cl2mP * dvx_p + clamP * dvz_p;
            tzzp1 = b_tzz + clamP * dvx_p + cl2mP * dvz_p;
            if (src_at_p) { txxp1 += w1; tzzp1 += w1; }
            txzp1 = b_txz + cmuP * ((vxq1 - vxp1) + (sh_vzp1[xp] - vzp1));
        }

        // ---- S1 rows 0, 1, 4, 5 ----
        #pragma unroll
        for (int rr = 0; rr < 4; ++rr) {
            const int r = (rr < 2) ? rr : RZ_ - 4 + rr;   // 0,1,4,5
            float vz_zm = (r > 0) ? vz[r - 1] : (has_top ? vza1 : vz[0]);
            float vx_zp = (r < RZ_ - 1) ? vx[r + 1] : (has_bot ? vxp1 : vx[r]);
            float dvx = vx[r] - s_vx[r][xm];
            float dvz = vz[r] - vz_zm;
            txx[r] += cl2m[r] * dvx + clam[r] * dvz;
            tzz[r] += clam[r] * dvx + cl2m[r] * dvz;
            txz[r] += cmu[r] * ((vx_zp - vx[r]) + (s_vz[r][xp] - vz[r]));
            if (is_src && r == src_lr) { txx[r] += w1; tzz[r] += w1; }
        }
        #pragma unroll
        for (int r = 0; r < RZ_; ++r) { s_txx[r][x] = txx[r]; s_txz[r][x] = txz[r]; }
        sh_txza1[x] = txza1; sh_txxp1[x] = txxp1;
        __syncthreads();   // (C)

        // ---- ghost t+2 edge velocities ----
        float vza2 = 0, vxp2 = 0;
        if (has_top)
            vza2 = vza1 + bA * ((txza1 - sh_txza1[xm]) + (tzz[0] - tzza1));
        if (has_bot)
            vxp2 = vxp1 + bP * ((sh_txxp1[xp] - txxp1) + (txzp1 - txz[RZ_ - 1]));

        // ------------------ V2 ------------------
        #pragma unroll
        for (int r = 0; r < RZ_; ++r) {
            float txx_c = txx[r], txz_c = txz[r];
            float txz_zm = (r > 0) ? txz[r - 1] : (has_top ? txza1 : txz_c);
            float tzz_zp = (r < RZ_ - 1) ? tzz[r + 1] : (has_bot ? tzzp1 : tzz[r]);
            vx[r] += bc[r] * ((s_txx[r][xp] - txx_c) + (txz_c - txz_zm));
            vz[r] += bc[r] * ((txz_c - s_txz[r][xm]) + (tzz_zp - tzz[r]));
            s_vx[r][x] = vx[r]; s_vz[r][x] = vz[r];
        }
        __syncthreads();   // (D)

        // ---- S2 rows 4,5 -> publish dn; rows 0,1 -> publish up ----
        const int pw = i & 1;
        #pragma unroll
        for (int rr = 0; rr < 2; ++rr) {
            const int r = RZ_ - 2 + rr;   // 4, 5
            float vz_zm = vz[r - 1];
            float vx_zp = (r < RZ_ - 1) ? vx[r + 1] : (has_bot ? vxp2 : vx[r]);
            float dvx = vx[r] - s_vx[r][xm];
            float dvz = vz[r] - vz_zm;
            txx[r] += cl2m[r] * dvx + clam[r] * dvz;
            tzz[r] += clam[r] * dvx + cl2m[r] * dvz;
            txz[r] += cmu[r] * ((vx_zp - vx[r]) + (s_vz[r][xp] - vz[r]));
            if (is_src && r == src_lr) { txx[r] += w2; tzz[r] += w2; }
        }
        {
            Chunk* dnp = &g_dnC[pw][c][0][0];
            stcg_v4(dnp + 0 * NX_ + x, vx[RZ_-1], txx[RZ_-1], txz[RZ_-1], i);
            stcg_v4(dnp + 1 * NX_ + x, vz[RZ_-1], tzz[RZ_-1], txz[RZ_-2], i);
            stcg_v4(dnp + 2 * NX_ + x, vz[RZ_-2], tzz[RZ_-2], 0.f,        i);
        }
        #pragma unroll
        for (int rr = 0; rr < 2; ++rr) {
            const int r = rr;             // 0, 1
            float vz_zm = (r > 0) ? vz[r - 1] : (has_top ? vza2 : vz[0]);
            float vx_zp = vx[r + 1];
            float dvx = vx[r] - s_vx[r][xm];
            float dvz = vz[r] - vz_zm;
            txx[r] += cl2m[r] * dvx + clam[r] * dvz;
            tzz[r] += clam[r] * dvx + cl2m[r] * dvz;
            txz[r] += cmu[r] * ((vx_zp - vx[r]) + (s_vz[r][xp] - vz[r]));
            if (is_src && r == src_lr) { txx[r] += w2; tzz[r] += w2; }
        }
        {
            Chunk* upp = &g_upC[pw][c][0][0];
            stcg_v4(upp + 0 * NX_ + x, vx[0],  txx[0], txz[0], i);
            stcg_v4(upp + 1 * NX_ + x, vz[0],  tzz[0], vx[1],  i);
            stcg_v4(upp + 2 * NX_ + x, txx[1], txz[1], tzz[1], i);
        }

        // record t2 (v mirrors valid since bar D; S2 doesn't touch them)
        if (is_rec) {
            int base = (t2 - 1) * (NREC_ * 2 * B_) + x * (2 * B_);
            out[base + b]      = s_vx[my_lrz][my_rx];
            out[base + B_ + b] = s_vz[my_lrz][my_rx];
        }

        // ---- S2 interior rows 2,3 (off the inter-CTA critical path) ----
        #pragma unroll
        for (int r = 2; r < RZ_ - 2; ++r) {
            float dvx = vx[r] - s_vx[r][xm];
            float dvz = vz[r] - vz[r - 1];
            txx[r] += cl2m[r] * dvx + clam[r] * dvz;
            tzz[r] += clam[r] * dvx + cl2m[r] * dvz;
            txz[r] += cmu[r] * ((vx[r + 1] - vx[r]) + (s_vz[r][xp] - vz[r]));
            if (is_src && r == src_lr) { txx[r] += w2; tzz[r] += w2; }
        }
        #pragma unroll
        for (int r = 0; r < RZ_; ++r) { s_txx[r][x] = txx[r]; s_txz[r][x] = txz[r]; }
        __syncthreads();   // (E) — next iter's V1 reads s_txx/s_txz
    }
}

extern "C" void kernel_launch(void* const* d_in, const int* in_sizes, int n_in,
                              void* d_out, int out_size) {
    const float* x   = (const float*)d_in[0];
    const float* vp  = (const float*)d_in[1];
    const float* vs  = (const float*)d_in[2];
    const float* rho = (const float*)d_in[3];
    const int* src   = (const int*)d_in[4];
    const int* rec   = (const int*)d_in[5];
    float* out = (float*)d_out;

    // re-zero message slots (tags -> 0) so every graph replay is identical
    int n = 2 * NCTA_ * 3 * NX_ * 4;
    init_msgs_kernel<<<(n + 255) / 256, 256>>>();
    wave_kernel<<<NCTA_, NX_>>>(x, vp, vs, rho, src, rec, out);
}

// round 13
// speedup vs baseline: 3.8275x; 1.1659x over previous
#include <cuda_runtime.h>

// ---------------------------------------------------------------------------
// 2-D elastic staggered-grid FDTD, persistent kernel, k=2 time blocking.
// R8 structure (the proven optimum of this session): one thread per column,
// 6 rows of all 5 fields in registers, SMEM x-neighbor mirrors, 4 barriers
// per 2-step iteration, and a TAGGED-CHUNK neighbor exchange: message
// payloads and the iteration tag travel in the same 16-byte
// st/ld.global.cg.v4, so the exchange costs ONE L2 round trip with no flags,
// no acquire/release, and no poll-broadcast barrier.
//
// Chunk layout per column x (slot = iter parity):
//   dn (c -> c+1, c's LAST rows):  A={vx5,txx5,txz5,tag} B={vz5,tzz5,txz4,tag}
//                                  C={vz4,tzz4,0,tag}
//   up (c -> c-1, c's FIRST rows): D={vx0,txx0,txz0,tag} E={vz0,tzz0,vx1,tag}
//                                  F={txx1,txz1,tzz1,tag}
//
// Race-safety: tag==i-1 equality poll; producer overwrite of slot i&1 cannot
// race a lagging reader because the producer's entry into iter i data-depends
// (through the neighbor's published values) on the neighbor having consumed
// the i-2 contents of that slot. 16B v4 accesses are single L2 transactions
// on sm_103a, so tag and payload are atomic per chunk.
//
// Output layout (reference): (NT, NREC, 2*B):
//   out[t*NREC*8 + r*8 + comp*4 + b], comp 0 = vx, comp 1 = vz.
// ---------------------------------------------------------------------------

namespace {
constexpr int B_    = 4;
constexpr int NT_   = 256;
constexpr int NZ_   = 192;
constexpr int NX_   = 192;
constexpr int NREC_ = 128;
constexpr int RZ_   = 6;                 // rows per tile
constexpr int NTILES_ = NZ_ / RZ_;       // 32
constexpr int NCTA_   = B_ * NTILES_;    // 128 (< 148 SMs -> all co-resident)
constexpr int NIT_    = NT_ / 2;         // 128 iterations
constexpr float DT_ = 0.001f;
constexpr float DH_ = 10.0f;
}

struct __align__(16) Chunk { float a, b, c; int tag; };

// double-buffered tagged message chunks: [slot][cta][chunk 0..2][x]
__device__ Chunk g_dnC[2][NCTA_][3][NX_];
__device__ Chunk g_upC[2][NCTA_][3][NX_];

__device__ __forceinline__ void ldcg_v4(const Chunk* p, float& a, float& b,
                                        float& c, int& t) {
    asm volatile("ld.global.cg.v4.b32 {%0,%1,%2,%3}, [%4];"
                 : "=f"(a), "=f"(b), "=f"(c), "=r"(t) : "l"(p));
}
__device__ __forceinline__ void stcg_v4(Chunk* p, float a, float b, float c, int t) {
    asm volatile("st.global.cg.v4.b32 [%0], {%1,%2,%3,%4};"
                 :: "l"(p), "f"(a), "f"(b), "f"(c), "r"(t) : "memory");
}

__global__ void init_msgs_kernel() {
    int i = blockIdx.x * blockDim.x + threadIdx.x;
    int n = 2 * NCTA_ * 3 * NX_ * 4;            // total 32-bit words per array
    if (i < n) {
        ((int*)g_dnC)[i] = 0;
        ((int*)g_upC)[i] = 0;
    }
}

__global__ void __launch_bounds__(NX_, 1) wave_kernel(
    const float* __restrict__ xsrc,    // (B, NT)
    const float* __restrict__ vp,      // (NZ, NX)
    const float* __restrict__ vs,
    const float* __restrict__ rho,
    const int*   __restrict__ src_loc, // (B, 2)
    const int*   __restrict__ rec_loc, // (NREC, 2)
    float*       __restrict__ out)     // (NT, NREC, 2*B)
{
    const int c  = blockIdx.x;
    const int b  = c / NTILES_;
    const int tz = c % NTILES_;
    const int x  = threadIdx.x;
    const bool has_top = (tz > 0);
    const bool has_bot = (tz < NTILES_ - 1);
    const int xm = (x == 0) ? 0 : x - 1;              // clamp -> zero diff at edge
    const int xp = (x == NX_ - 1) ? NX_ - 1 : x + 1;

    __shared__ float s_vx [RZ_][NX_];
    __shared__ float s_vz [RZ_][NX_];
    __shared__ float s_txx[RZ_][NX_];
    __shared__ float s_txz[RZ_][NX_];
    // ghost staging rows (x-shifted reads of computed ghosts)
    __shared__ float sh_vxa1[NX_], sh_vza1[NX_], sh_txza1[NX_];
    __shared__ float sh_vxp1[NX_], sh_vzp1[NX_], sh_txxp1[NX_];

    // per-cell material coefficients (DT, 1/DH folded in)
    float bc[RZ_], cl2m[RZ_], clam[RZ_], cmu[RZ_];
    #pragma unroll
    for (int r = 0; r < RZ_; ++r) {
        int gi = (tz * RZ_ + r) * NX_ + x;
        float vpv = __ldg(&vp[gi]);
        float vsv = __ldg(&vs[gi]);
        float rh  = __ldg(&rho[gi]);
        float mu  = rh * vsv * vsv;
        float lam = rh * (vpv * vpv - 2.0f * vsv * vsv);
        bc[r]   = DT_ / (rh * DH_);
        cl2m[r] = (DT_ / DH_) * (lam + 2.0f * mu);
        clam[r] = (DT_ / DH_) * lam;
        cmu[r]  = (DT_ / DH_) * mu;
    }
    // ghost-row coefficients: a=z0-1, b=z0-2 (top), p=z1+1, q=z1+2 (bottom)
    float bA=0, bB=0, clamA=0, cl2mA=0, cmuA=0;
    float bP=0, bQ=0, clamP=0, cl2mP=0, cmuP=0;
    if (has_top) {
        int ga = (tz * RZ_ - 1) * NX_ + x;
        int gb = (tz * RZ_ - 2) * NX_ + x;
        float vpv = __ldg(&vp[ga]), vsv = __ldg(&vs[ga]), rh = __ldg(&rho[ga]);
        float mu  = rh * vsv * vsv;
        float lam = rh * (vpv * vpv - 2.0f * vsv * vsv);
        bA = DT_ / (rh * DH_);
        cl2mA = (DT_ / DH_) * (lam + 2.0f * mu);
        clamA = (DT_ / DH_) * lam;
        cmuA  = (DT_ / DH_) * mu;
        bB = DT_ / (__ldg(&rho[gb]) * DH_);
    }
    if (has_bot) {
        int gp = (tz * RZ_ + RZ_) * NX_ + x;
        int gq = (tz * RZ_ + RZ_ + 1) * NX_ + x;
        float vpv = __ldg(&vp[gp]), vsv = __ldg(&vs[gp]), rh = __ldg(&rho[gp]);
        float mu  = rh * vsv * vsv;
        float lam = rh * (vpv * vpv - 2.0f * vsv * vsv);
        bP = DT_ / (rh * DH_);
        cl2mP = (DT_ / DH_) * (lam + 2.0f * mu);
        clamP = (DT_ / DH_) * lam;
        cmuP  = (DT_ / DH_) * mu;
        bQ = DT_ / (__ldg(&rho[gq]) * DH_);
    }

    // wavefields, zero initial conditions
    float vx[RZ_]  = {}, vz[RZ_]  = {};
    float txx[RZ_] = {}, tzz[RZ_] = {}, txz[RZ_] = {};
    #pragma unroll
    for (int r = 0; r < RZ_; ++r) {
        s_vx[r][x] = 0.f; s_vz[r][x] = 0.f; s_txx[r][x] = 0.f; s_txz[r][x] = 0.f;
    }

    // source ownership
    const int ssz = src_loc[2 * b];
    const int ssx = src_loc[2 * b + 1];
    const bool is_src = ((ssz / RZ_) == tz) && (x == ssx);
    const int src_lr  = ssz % RZ_;
    const bool src_at_a = has_top && (ssz == tz * RZ_ - 1)  && (x == ssx);
    const bool src_at_p = has_bot && (ssz == tz * RZ_ + RZ_) && (x == ssx);

    // receiver ownership: thread index doubles as receiver index
    bool is_rec = false;
    int my_lrz = 0, my_rx = 0;
    if (x < NREC_) {
        int rz = rec_loc[2 * x];
        my_rx  = rec_loc[2 * x + 1];
        if ((rz / RZ_) == tz) { is_rec = true; my_lrz = rz % RZ_; }
    }

    // loop-invariant bases
    const float2* xsrc2 = reinterpret_cast<const float2*>(xsrc + b * NT_);

    __syncthreads();

    for (int i = 1; i <= NIT_; ++i) {
        const int t1 = 2 * i - 1;
        const int t2 = 2 * i;
        const float2 wv = __ldg(&xsrc2[i - 1]);   // {xsrc[t1-1], xsrc[t2-1]}
        const float w1 = wv.x;
        const float w2 = wv.y;

        // ---- V1 interior rows 1..RZ-2 (no message dependence) ----
        #pragma unroll
        for (int r = 1; r < RZ_ - 1; ++r) {
            float txx_c = txx[r], txz_c = txz[r];
            vx[r] += bc[r] * ((s_txx[r][xp] - txx_c) + (txz_c - txz[r - 1]));
            vz[r] += bc[r] * ((txz_c - s_txz[r][xm]) + (tzz[r + 1] - tzz[r]));
        }

        // ---- per-lane tagged message poll (ONE RTT, no barrier) ----
        const int want = i - 1;
        const int pr = want & 1;
        // top side values (from c-1's dn)
        float t_vx=0, t_txx_x=0, t_txz_x=0, t_txx_xp=0, t_txz_xm=0;
        float t_vz=0, t_tzz=0, t_txz2=0, t_txz2_xm=0, t_vz2=0, t_tzz2=0;
        // bottom side values (from c+1's up)
        float b_vx=0, b_txx_x=0, b_txz_x=0, b_txx_xp=0, b_txz_xm=0;
        float b_vz=0, b_tzz=0, b_vx2=0, b_txx2=0, b_txz2=0, b_tzz2=0, b_txx2_xp=0;
        {
            const Chunk* dn = has_top ? &g_dnC[pr][c - 1][0][0] : nullptr;
            const Chunk* up = has_bot ? &g_upC[pr][c + 1][0][0] : nullptr;
            bool top_ok = !has_top, bot_ok = !has_bot;
            do {
                if (!top_ok) {
                    int g0,g1,g2,g3,g4,g5; float u;
                    ldcg_v4(dn + 0*NX_ + x,  t_vx,   t_txx_x, t_txz_x,  g0);
                    ldcg_v4(dn + 0*NX_ + xm, u,      u,       t_txz_xm, g1);
                    ldcg_v4(dn + 0*NX_ + xp, u,      t_txx_xp,u,        g2);
                    ldcg_v4(dn + 1*NX_ + x,  t_vz,   t_tzz,   t_txz2,   g3);
                    ldcg_v4(dn + 1*NX_ + xm, u,      u,       t_txz2_xm,g4);
                    ldcg_v4(dn + 2*NX_ + x,  t_vz2,  t_tzz2,  u,        g5);
                    top_ok = (g0==want)&(g1==want)&(g2==want)&(g3==want)&(g4==want)&(g5==want);
                }
                if (!bot_ok) {
                    int g0,g1,g2,g3,g4,g5; float u;
                    ldcg_v4(up + 0*NX_ + x,  b_vx,   b_txx_x, b_txz_x,  g0);
                    ldcg_v4(up + 0*NX_ + xm, u,      u,       b_txz_xm, g1);
                    ldcg_v4(up + 0*NX_ + xp, u,      b_txx_xp,u,        g2);
                    ldcg_v4(up + 1*NX_ + x,  b_vz,   b_tzz,   b_vx2,    g3);
                    ldcg_v4(up + 2*NX_ + x,  b_txx2, b_txz2,  b_tzz2,   g4);
                    ldcg_v4(up + 2*NX_ + xp, b_txx2_xp, u,    u,        g5);
                    bot_ok = (g0==want)&(g1==want)&(g2==want)&(g3==want)&(g4==want)&(g5==want);
                }
            } while (!(top_ok && bot_ok));
        }
        // overlap: independent interior SMEM stores
        #pragma unroll
        for (int r = 1; r < RZ_ - 1; ++r) { s_vx[r][x] = vx[r]; s_vz[r][x] = vz[r]; }

        // ---- ghost t+1 velocities ----
        float vza1=0, vzb1=0, vxa1=0, vxp1=0, vxq1=0, vzp1=0;
        if (has_top) {
            vza1 = t_vz  + bA * ((t_txz_x  - t_txz_xm)  + (tzz[0] - t_tzz));
            vzb1 = t_vz2 + bB * ((t_txz2   - t_txz2_xm) + (t_tzz  - t_tzz2));
            vxa1 = t_vx  + bA * ((t_txx_xp - t_txx_x)   + (t_txz_x - t_txz2));
        }
        if (has_bot) {
            vxp1 = b_vx  + bP * ((b_txx_xp  - b_txx_x) + (b_txz_x - txz[RZ_ - 1]));
            vxq1 = b_vx2 + bQ * ((b_txx2_xp - b_txx2)  + (b_txz2  - b_txz_x));
            vzp1 = b_vz  + bP * ((b_txz_x   - b_txz_xm) + (b_tzz2 - b_tzz));
        }

        // ---- V1 edge rows 0 and RZ-1 ----
        {
            float txz_zm = has_top ? t_txz_x : txz[0];
            vx[0] += bc[0] * ((s_txx[0][xp] - txx[0]) + (txz[0] - txz_zm));
            vz[0] += bc[0] * ((txz[0] - s_txz[0][xm]) + (tzz[1] - tzz[0]));
            constexpr int r = RZ_ - 1;
            float tzz_zp = has_bot ? b_tzz : tzz[r];
            vx[r] += bc[r] * ((s_txx[r][xp] - txx[r]) + (txz[r] - txz[r - 1]));
            vz[r] += bc[r] * ((txz[r] - s_txz[r][xm]) + (tzz_zp - tzz[r]));
        }
        s_vx[0][x] = vx[0];             s_vz[0][x] = vz[0];
        s_vx[RZ_ - 1][x] = vx[RZ_ - 1]; s_vz[RZ_ - 1][x] = vz[RZ_ - 1];
        sh_vxa1[x] = vxa1; sh_vza1[x] = vza1;
        sh_vxp1[x] = vxp1; sh_vzp1[x] = vzp1;
        __syncthreads();   // (2)

        // record t1
        if (is_rec) {
            int base = (t1 - 1) * (NREC_ * 2 * B_) + x * (2 * B_);
            out[base + b]      = s_vx[my_lrz][my_rx];
            out[base + B_ + b] = s_vz[my_lrz][my_rx];
        }

        // ---- ghost t+1 edge stresses ----
        float tzza1=0, txza1=0, txxp1=0, tzzp1=0, txzp1=0;
        if (has_top) {
            tzza1 = t_tzz + clamA * (vxa1 - sh_vxa1[xm]) + cl2mA * (vza1 - vzb1);
            if (src_at_a) tzza1 += w1;
            txza1 = t_txz_x + cmuA * ((vx[0] - vxa1) + (sh_vza1[xp] - vza1));
        }
        if (has_bot) {
            float dvx_p = vxp1 - sh_vxp1[xm];
            float dvz_p = vzp1 - vz[RZ_ - 1];
            txxp1 = b_txx_x + cl2mP * dvx_p + clamP * dvz_p;
            tzzp1 = b_tzz   + clamP * dvx_p + cl2mP * dvz_p;
            if (src_at_p) { txxp1 += w1; tzzp1 += w1; }
            txzp1 = b_txz_x + cmuP * ((vxq1 - vxp1) + (sh_vzp1[xp] - vzp1));
        }

        // ------------------ S1 ------------------
        #pragma unroll
        for (int r = 0; r < RZ_; ++r) {
            float vx_c = vx[r], vz_c = vz[r];
            float vz_zm = (r > 0) ? vz[r - 1] : (has_top ? vza1 : vz_c);
            float vx_zp = (r < RZ_ - 1) ? vx[r + 1] : (has_bot ? vxp1 : vx_c);
            float dvx = vx_c - s_vx[r][xm];
            float dvz = vz_c - vz_zm;
            txx[r] += cl2m[r] * dvx + clam[r] * dvz;
            tzz[r] += clam[r] * dvx + cl2m[r] * dvz;
            txz[r] += cmu[r] * ((vx_zp - vx_c) + (s_vz[r][xp] - vz_c));
        }
        if (is_src) {
            #pragma unroll
            for (int r = 0; r < RZ_; ++r)
                if (r == src_lr) { txx[r] += w1; tzz[r] += w1; }
        }
        #pragma unroll
        for (int r = 0; r < RZ_; ++r) { s_txx[r][x] = txx[r]; s_txz[r][x] = txz[r]; }
        sh_txza1[x] = txza1; sh_txxp1[x] = txxp1;
        __syncthreads();   // (3)

        // ---- ghost t+2 edge velocities ----
        float vza2 = 0, vxp2 = 0;
        if (has_top)
            vza2 = vza1 + bA * ((txza1 - sh_txza1[xm]) + (tzz[0] - tzza1));
        if (has_bot)
            vxp2 = vxp1 + bP * ((sh_txxp1[xp] - txxp1) + (txzp1 - txz[RZ_ - 1]));

        // ------------------ V2 ------------------
        #pragma unroll
        for (int r = 0; r < RZ_; ++r) {
            float txx_c = txx[r], txz_c = txz[r];
            float txz_zm = (r > 0) ? txz[r - 1] : (has_top ? txza1 : txz_c);
            float tzz_zp = (r < RZ_ - 1) ? tzz[r + 1] : (has_bot ? tzzp1 : tzz[r]);
            vx[r] += bc[r] * ((s_txx[r][xp] - txx_c) + (txz_c - txz_zm));
            vz[r] += bc[r] * ((txz_c - s_txz[r][xm]) + (tzz_zp - tzz[r]));
        }
        #pragma unroll
        for (int r = 0; r < RZ_; ++r) { s_vx[r][x] = vx[r]; s_vz[r][x] = vz[r]; }
        __syncthreads();   // (4)

        // ---- S2 apron rows {0,1,RZ-2,RZ-1} first, then per-lane publish ----
        #pragma unroll
        for (int rr = 0; rr < 4; ++rr) {
            const int r = (rr < 2) ? rr : RZ_ - 4 + rr;   // 0,1,RZ-2,RZ-1
            float vx_c = vx[r], vz_c = vz[r];
            float vz_zm = (r > 0) ? vz[r - 1] : (has_top ? vza2 : vz_c);
            float vx_zp = (r < RZ_ - 1) ? vx[r + 1] : (has_bot ? vxp2 : vx_c);
            float dvx = vx_c - s_vx[r][xm];
            float dvz = vz_c - vz_zm;
            txx[r] += cl2m[r] * dvx + clam[r] * dvz;
            tzz[r] += clam[r] * dvx + cl2m[r] * dvz;
            txz[r] += cmu[r] * ((vx_zp - vx_c) + (s_vz[r][xp] - vz_c));
            if (is_src && r == src_lr) { txx[r] += w2; tzz[r] += w2; }
        }
        // publish t+2 apron, tag = i (per-lane, no barrier, no flag)
        {
            const int pw = i & 1;
            Chunk* dnp = &g_dnC[pw][c][0][0];
            stcg_v4(dnp + 0*NX_ + x, vx[RZ_-1], txx[RZ_-1], txz[RZ_-1], i);
            stcg_v4(dnp + 1*NX_ + x, vz[RZ_-1], tzz[RZ_-1], txz[RZ_-2], i);
            stcg_v4(dnp + 2*NX_ + x, vz[RZ_-2], tzz[RZ_-2], 0.f,        i);
            Chunk* upp = &g_upC[pw][c][0][0];
            stcg_v4(upp + 0*NX_ + x, vx[0], txx[0], txz[0], i);
            stcg_v4(upp + 1*NX_ + x, vz[0], tzz[0], vx[1],  i);
            stcg_v4(upp + 2*NX_ + x, txx[1], txz[1], tzz[1], i);
        }

        // record t2 (s_vx/s_vz valid since sync 4; S2 doesn't touch them)
        if (is_rec) {
            int base = (t2 - 1) * (NREC_ * 2 * B_) + x * (2 * B_);
            out[base + b]      = s_vx[my_lrz][my_rx];
            out[base + B_ + b] = s_vz[my_lrz][my_rx];
        }

        // ---- S2 interior rows 2..RZ-3 (off the inter-CTA critical path) ----
        #pragma unroll
        for (int r = 2; r < RZ_ - 2; ++r) {
            float vx_c = vx[r], vz_c = vz[r];
            float dvx = vx_c - s_vx[r][xm];
            float dvz = vz_c - vz[r - 1];
            txx[r] += cl2m[r] * dvx + clam[r] * dvz;
            tzz[r] += clam[r] * dvx + cl2m[r] * dvz;
            txz[r] += cmu[r] * ((vx[r + 1] - vx_c) + (s_vz[r][xp] - vz_c));
            if (is_src && r == src_lr) { txx[r] += w2; tzz[r] += w2; }
        }
        #pragma unroll
        for (int r = 0; r < RZ_; ++r) { s_txx[r][x] = txx[r]; s_txz[r][x] = txz[r]; }
        __syncthreads();   // (6) — next iter's V1 reads s_txx/s_txz
    }
}

extern "C" void kernel_launch(void* const* d_in, const int* in_sizes, int n_in,
                              void* d_out, int out_size) {
    const float* x   = (const float*)d_in[0];
    const float* vp  = (const float*)d_in[1];
    const float* vs  = (const float*)d_in[2];
    const float* rho = (const float*)d_in[3];
    const int* src   = (const int*)d_in[4];
    const int* rec   = (const int*)d_in[5];
    float* out = (float*)d_out;

    // re-zero message slots (tags -> 0) so every graph replay is identical
    int n = 2 * NCTA_ * 3 * NX_ * 4;
    init_msgs_kernel<<<(n + 255) / 256, 256>>>();
    wave_kernel<<<NCTA_, NX_>>>(x, vp, vs, rho, src, rec, out);
}